// round 9
// baseline (speedup 1.0000x reference)
#include <cuda_runtime.h>
#include <math.h>
#include <stdint.h>

// Problem constants
#define Bn   4
#define Sn   1024
#define Dn   1024
#define Hn   16
#define DHn  64
#define NNEUR 16384
#define TOPK 16
#define NCAND 48
#define MTOK (Bn * Sn)   // 4096 tokens

// ---------------------------------------------------------------------------
// Scratch (device globals; no cudaMalloc allowed)
// ---------------------------------------------------------------------------
__device__ float g_q[MTOK * Dn];
__device__ float g_k[MTOK * Dn];
__device__ float g_v[MTOK * Dn];
__device__ float g_ctx[MTOK * Dn];
__device__ float g_y[MTOK * Dn];
__device__ float g_gate[MTOK * 2];
// Reused: attention logits [B*H, S, S] (67.1M) then coarse scores [B*S, N]
__device__ float g_big[(size_t)MTOK * NNEUR];

// ---------------------------------------------------------------------------
// Accurate expf (~1-2 ulp), independent of -use_fast_math (never calls expf).
// ---------------------------------------------------------------------------
__device__ __forceinline__ float exp_acc(float x) {
  if (x < -87.3f) return 0.0f;
  float t = __fmaf_rn(x, 1.44269504088896340736f, 12582912.0f);
  float k = __fsub_rn(t, 12582912.0f);           // round-to-nearest(x*log2e)
  float r = __fmaf_rn(k, -0.693359375f, x);      // Cody-Waite hi
  r = __fmaf_rn(k, 2.12194440e-4f, r);           // Cody-Waite lo
  float p = 1.9841269841269841e-4f;              // 1/5040
  p = __fmaf_rn(p, r, 1.3888888888888889e-3f);   // 1/720
  p = __fmaf_rn(p, r, 8.3333333333333333e-3f);   // 1/120
  p = __fmaf_rn(p, r, 4.1666666666666664e-2f);   // 1/24
  p = __fmaf_rn(p, r, 1.6666666666666666e-1f);   // 1/6
  p = __fmaf_rn(p, r, 0.5f);
  p = __fmaf_rn(p, r, 1.0f);
  p = __fmaf_rn(p, r, 1.0f);
  return ldexpf(p, (int)k);
}

// ---------------------------------------------------------------------------
// SGEMM, serial-ascending-k single-accumulator FMA per output element
// (emulates Eigen gebp / cuBLAS mainloop rounding). 128x128 tile, K-tile 8.
// BT=false: C = A[M,K] @ B[K,N]; BT=true: C = A[M,K] @ B[N,K]^T.
// ---------------------------------------------------------------------------
template <bool BT, bool BIAS>
__global__ __launch_bounds__(256, 2) void sgemm128(
    const float* __restrict__ A, const float* __restrict__ Bm,
    const float* __restrict__ bias, float* __restrict__ C,
    int M, int N, int K) {
  __shared__ float As[8][128];
  __shared__ float Bs[8][128];
  const int tid = threadIdx.x;
  const int m0 = blockIdx.y * 128;
  const int n0 = blockIdx.x * 128;
  const int ty = tid >> 4;   // 0..15
  const int tx = tid & 15;   // 0..15

  float acc[8][8];
#pragma unroll
  for (int i = 0; i < 8; i++)
#pragma unroll
    for (int j = 0; j < 8; j++) acc[i][j] = 0.f;

  const int lrow = tid >> 1;        // 0..127
  const int lcol = (tid & 1) * 4;   // 0 or 4
  const int krow = tid >> 5;        // 0..7
  const int kcol = (tid & 31) * 4;  // 0..124

  for (int k0 = 0; k0 < K; k0 += 8) {
    float4 av = *(const float4*)(A + (size_t)(m0 + lrow) * K + k0 + lcol);
    As[lcol + 0][lrow] = av.x;
    As[lcol + 1][lrow] = av.y;
    As[lcol + 2][lrow] = av.z;
    As[lcol + 3][lrow] = av.w;
    if (BT) {
      float4 bv = *(const float4*)(Bm + (size_t)(n0 + lrow) * K + k0 + lcol);
      Bs[lcol + 0][lrow] = bv.x;
      Bs[lcol + 1][lrow] = bv.y;
      Bs[lcol + 2][lrow] = bv.z;
      Bs[lcol + 3][lrow] = bv.w;
    } else {
      float4 bv = *(const float4*)(Bm + (size_t)(k0 + krow) * N + n0 + kcol);
      *(float4*)&Bs[krow][kcol] = bv;
    }
    __syncthreads();
#pragma unroll
    for (int kk = 0; kk < 8; kk++) {   // ascending k, serial accumulator
      float a[8], b[8];
      *(float4*)(a)     = *(const float4*)&As[kk][ty * 8];
      *(float4*)(a + 4) = *(const float4*)&As[kk][ty * 8 + 4];
      *(float4*)(b)     = *(const float4*)&Bs[kk][tx * 8];
      *(float4*)(b + 4) = *(const float4*)&Bs[kk][tx * 8 + 4];
#pragma unroll
      for (int i = 0; i < 8; i++)
#pragma unroll
        for (int j = 0; j < 8; j++)
          acc[i][j] = __fmaf_rn(a[i], b[j], acc[i][j]);
    }
    __syncthreads();
  }

  float bj[8];
#pragma unroll
  for (int j = 0; j < 8; j++) bj[j] = BIAS ? bias[n0 + tx * 8 + j] : 0.f;

#pragma unroll
  for (int i = 0; i < 8; i++) {
    const int row = m0 + ty * 8 + i;
    float* cp = C + (size_t)row * N + n0 + tx * 8;
    float4 o0 = make_float4(__fadd_rn(acc[i][0], bj[0]), __fadd_rn(acc[i][1], bj[1]),
                            __fadd_rn(acc[i][2], bj[2]), __fadd_rn(acc[i][3], bj[3]));
    float4 o1 = make_float4(__fadd_rn(acc[i][4], bj[4]), __fadd_rn(acc[i][5], bj[5]),
                            __fadd_rn(acc[i][6], bj[6]), __fadd_rn(acc[i][7], bj[7]));
    *(float4*)(cp) = o0;
    *(float4*)(cp + 4) = o1;
  }
}

// ---------------------------------------------------------------------------
// Attention logits: L[sq,sk] = fl(serial ascending d: Q.K) * 0.125
// ---------------------------------------------------------------------------
__global__ __launch_bounds__(128) void attn_logits_kernel(
    const float* __restrict__ q, const float* __restrict__ k,
    float* __restrict__ logits) {
  const int bh = blockIdx.z;
  const int b = bh >> 4, h = bh & 15;
  const int sq0 = blockIdx.y * 64;
  const int sk0 = blockIdx.x * 64;
  __shared__ float Qs[64][65];
  __shared__ float Ks[64][65];
  const int tid = threadIdx.x;

  for (int i = tid; i < 64 * 16; i += 128) {
    const int r = i >> 4;
    const int c = (i & 15) * 4;
    float4 vq = *(const float4*)(q + (size_t)(b * Sn + sq0 + r) * Dn + h * DHn + c);
    Qs[r][c] = vq.x; Qs[r][c + 1] = vq.y; Qs[r][c + 2] = vq.z; Qs[r][c + 3] = vq.w;
    float4 vk = *(const float4*)(k + (size_t)(b * Sn + sk0 + r) * Dn + h * DHn + c);
    Ks[r][c] = vk.x; Ks[r][c + 1] = vk.y; Ks[r][c + 2] = vk.z; Ks[r][c + 3] = vk.w;
  }
  __syncthreads();

  const int ty = tid >> 4;  // 0..7 -> 8 rows each
  const int tx = tid & 15;  // 0..15 -> 4 cols each
  float acc[8][4] = {};
  for (int kk = 0; kk < 64; kk++) {   // ascending d, serial
    float a[8], bb[4];
#pragma unroll
    for (int i = 0; i < 8; i++) a[i] = Qs[ty * 8 + i][kk];
#pragma unroll
    for (int j = 0; j < 4; j++) bb[j] = Ks[tx * 4 + j][kk];
#pragma unroll
    for (int i = 0; i < 8; i++)
#pragma unroll
      for (int j = 0; j < 4; j++) acc[i][j] = __fmaf_rn(a[i], bb[j], acc[i][j]);
  }

#pragma unroll
  for (int i = 0; i < 8; i++) {
    float* lp = logits + ((size_t)bh * Sn + sq0 + ty * 8 + i) * Sn + sk0 + tx * 4;
#pragma unroll
    for (int j = 0; j < 4; j++)
      lp[j] = __fmul_rn(acc[i][j], 0.125f);   // /sqrt(64): exact pow2
  }
}

// ---------------------------------------------------------------------------
// Row softmax (length 1024): exact max, exp_acc, SERIAL ASCENDING sum by
// lane 0, correctly-rounded divide. One warp per row; 8 rows per block.
// ---------------------------------------------------------------------------
__global__ __launch_bounds__(256) void softmax_serial(float* __restrict__ data) {
  const int w = threadIdx.x >> 5;
  const int lane = threadIdx.x & 31;
  float* p = data + ((size_t)blockIdx.x * 8 + w) * 1024;
  __shared__ float buf[8][1024];
  __shared__ float ssum[8];

  float mx = -INFINITY;
  for (int d = lane; d < 1024; d += 32) {
    const float v = p[d];
    buf[w][d] = v;
    mx = fmaxf(mx, v);
  }
#pragma unroll
  for (int off = 16; off; off >>= 1)
    mx = fmaxf(mx, __shfl_xor_sync(0xffffffffu, mx, off));

  for (int d = lane; d < 1024; d += 32)
    buf[w][d] = exp_acc(__fsub_rn(buf[w][d], mx));
  __syncwarp();
  if (lane == 0) {
    float s = 0.f;
    for (int d = 0; d < 1024; d++) s = __fadd_rn(s, buf[w][d]);  // serial asc
    ssum[w] = s;
  }
  __syncwarp();
  const float S = ssum[w];
  for (int d = lane; d < 1024; d += 32)
    p[d] = __fdiv_rn(buf[w][d], S);
}

// ---------------------------------------------------------------------------
// context = attn @ V, serial ascending over sk (S=1024), fp32 FMA chain,
// written in [B, S, H*DH] layout.
// ---------------------------------------------------------------------------
__global__ __launch_bounds__(128) void attn_av_kernel(
    const float* __restrict__ pm, const float* __restrict__ v,
    float* __restrict__ ctx) {
  const int bh = blockIdx.y;
  const int b = bh >> 4, h = bh & 15;
  const int sq0 = blockIdx.x * 64;
  __shared__ float Ps[64][65];
  __shared__ float Vs[64][65];
  const int tid = threadIdx.x;
  const int ty = tid >> 4;
  const int tx = tid & 15;
  float acc[8][4] = {};

  for (int sk0 = 0; sk0 < Sn; sk0 += 64) {   // ascending sk tiles
    for (int i = tid; i < 64 * 16; i += 128) {
      const int r = i >> 4;
      const int c = (i & 15) * 4;
      float4 pv = *(const float4*)(pm + ((size_t)bh * Sn + sq0 + r) * Sn + sk0 + c);
      Ps[r][c] = pv.x; Ps[r][c + 1] = pv.y; Ps[r][c + 2] = pv.z; Ps[r][c + 3] = pv.w;
      float4 vv = *(const float4*)(v + (size_t)(b * Sn + sk0 + r) * Dn + h * DHn + c);
      Vs[r][c] = vv.x; Vs[r][c + 1] = vv.y; Vs[r][c + 2] = vv.z; Vs[r][c + 3] = vv.w;
    }
    __syncthreads();
    for (int kk = 0; kk < 64; kk++) {        // ascending within tile
      float a[8], bb[4];
#pragma unroll
      for (int i = 0; i < 8; i++) a[i] = Ps[ty * 8 + i][kk];
#pragma unroll
      for (int j = 0; j < 4; j++) bb[j] = Vs[kk][tx * 4 + j];
#pragma unroll
      for (int i = 0; i < 8; i++)
#pragma unroll
        for (int j = 0; j < 4; j++) acc[i][j] = __fmaf_rn(a[i], bb[j], acc[i][j]);
    }
    __syncthreads();
  }

#pragma unroll
  for (int i = 0; i < 8; i++) {
    float* cp = ctx + (size_t)(b * Sn + sq0 + ty * 8 + i) * Dn + h * DHn + tx * 4;
    *(float4*)cp = make_float4(acc[i][0], acc[i][1], acc[i][2], acc[i][3]);
  }
}

// ---------------------------------------------------------------------------
// Gate: logits via SERIAL ASCENDING fp32 FMA over the 2048-concat order
// (x[0..1023] then ctx[0..1023]), one thread per logit. Then emulated
// 2-way softmax, stored; y = w0*x + w1*ctx feeds the coarse GEMM only.
// ---------------------------------------------------------------------------
__global__ __launch_bounds__(256) void gate_combine_serial(
    const float* __restrict__ x, const float* __restrict__ ctx,
    const float* __restrict__ pw, const float* __restrict__ pb,
    float* __restrict__ y, float* __restrict__ gate) {
  const int t = blockIdx.x;
  const int tid = threadIdx.x;
  __shared__ float xs[Dn];
  __shared__ float cs[Dn];
  __shared__ float lg[2];
  __shared__ float w01[2];

  const float* xr = x + (size_t)t * Dn;
  const float* cr = ctx + (size_t)t * Dn;
  for (int d = tid * 4; d < Dn; d += 256 * 4) {
    *(float4*)&xs[d] = *(const float4*)(xr + d);
    *(float4*)&cs[d] = *(const float4*)(cr + d);
  }
  __syncthreads();

  if (tid < 2) {
    const int col = tid;
    float l = 0.f;
    for (int d = 0; d < Dn; d++)                      // x part, ascending
      l = __fmaf_rn(xs[d], pw[2 * d + col], l);
    for (int d = 0; d < Dn; d++)                      // ctx part, ascending
      l = __fmaf_rn(cs[d], pw[2 * (Dn + d) + col], l);
    lg[col] = __fadd_rn(l, pb[col]);                  // +bias (elementwise op)
  }
  __syncthreads();
  if (tid == 0) {
    const float l0 = lg[0], l1 = lg[1];
    const float m = fmaxf(l0, l1);
    const float e0 = exp_acc(__fsub_rn(l0, m));
    const float e1 = exp_acc(__fsub_rn(l1, m));
    const float S = __fadd_rn(e0, e1);                // ascending sum
    w01[0] = __fdiv_rn(e0, S);
    w01[1] = __fdiv_rn(e1, S);
    gate[2 * t] = w01[0];
    gate[2 * t + 1] = w01[1];
  }
  __syncthreads();
  const float w0 = w01[0], w1 = w01[1];
  for (int d = tid; d < Dn; d += 256)
    y[(size_t)t * Dn + d] = w0 * xs[d] + w1 * cs[d];  // coarse path only
}

// ---------------------------------------------------------------------------
// Candidate top-48 (fast coarse) -> SERIAL fp32 rescore (Eigen-order) ->
// top-16 with jax tie-break -> emulated softmax -> outputs.
// ---------------------------------------------------------------------------
__global__ __launch_bounds__(256) void refine_topk_kernel(
    const float* __restrict__ coarse, const float* __restrict__ x,
    const float* __restrict__ ctx, const float* __restrict__ neurons,
    const float* __restrict__ gate,
    float* __restrict__ out_y, float* __restrict__ out_idx,
    float* __restrict__ out_w, float* __restrict__ out_sel) {
  const int t = blockIdx.x;
  const int tid = threadIdx.x;
  const int lane = tid & 31;
  const int warp = tid >> 5;

  __shared__ float x_s[Dn];
  __shared__ float c_s[Dn];
  __shared__ float nbuf[8][Dn];     // 32KB: 8 staged neuron rows
  __shared__ float rv[256];
  __shared__ int ri[256];
  __shared__ int cand[NCAND];
  __shared__ float resc[NCAND];
  __shared__ float scratch[16];
  __shared__ int topi[TOPK];
  __shared__ float wts[TOPK];

  {
    const float* xr = x + (size_t)t * Dn;
    const float* cr = ctx + (size_t)t * Dn;
    for (int d = tid * 4; d < Dn; d += 256 * 4) {
      *(float4*)&x_s[d] = *(const float4*)(xr + d);
      *(float4*)&c_s[d] = *(const float4*)(cr + d);
    }
  }
  __syncthreads();

  // ---- Coarse top-NCAND candidate selection ----
  float sv[64];
  {
    const float* sr = coarse + (size_t)t * NNEUR;
#pragma unroll
    for (int j = 0; j < 64; j++) sv[j] = sr[j * 256 + tid];
  }
  float bv = -INFINITY;
  int bj = 0;
#pragma unroll
  for (int j = 0; j < 64; j++)
    if (sv[j] > bv) { bv = sv[j]; bj = j; }

  for (int r = 0; r < NCAND; r++) {
    rv[tid] = bv;
    ri[tid] = bj * 256 + tid;
    __syncthreads();
    for (int off = 128; off; off >>= 1) {
      if (tid < off) {
        const float v2 = rv[tid + off];
        const int i2 = ri[tid + off];
        if (v2 > rv[tid] || (v2 == rv[tid] && i2 < ri[tid])) {
          rv[tid] = v2; ri[tid] = i2;
        }
      }
      __syncthreads();
    }
    const int widx = ri[0];
    if (tid == 0) cand[r] = widx;
    if ((widx & 255) == tid) {
      sv[widx >> 8] = -INFINITY;
      bv = -INFINITY; bj = 0;
#pragma unroll
      for (int j = 0; j < 64; j++)
        if (sv[j] > bv) { bv = sv[j]; bj = j; }
    }
    __syncthreads();
  }

  // ---- Serial rescore: waves of 8 candidates ----
  const float w0 = gate[2 * t], w1 = gate[2 * t + 1];
  for (int wave = 0; wave < NCAND / 8; wave++) {
    const int ci = wave * 8 + warp;
    const float* nr = neurons + (size_t)cand[ci] * Dn;
    for (int d = lane * 4; d < Dn; d += 32 * 4)
      *(float4*)&nbuf[warp][d] = *(const float4*)(nr + d);
    __syncthreads();
    if (tid < 16) {
      const int c = tid >> 1;
      const float* vrow = (tid & 1) ? c_s : x_s;
      float acc = 0.f;
      for (int d = 0; d < Dn; d++)                 // serial ascending FMA
        acc = __fmaf_rn(vrow[d], nbuf[c][d], acc);
      scratch[tid] = acc;
    }
    __syncthreads();
    if (tid < 8) {
      const float tsr = scratch[2 * tid];          // fp32 token score
      const float csr = scratch[2 * tid + 1];      // fp32 context score
      resc[wave * 8 + tid] = __fadd_rn(__fmul_rn(w0, tsr), __fmul_rn(w1, csr));
    }
    __syncthreads();
  }

  // ---- Top-16 among NCAND: value desc, tie -> lower index ----
  if (tid == 0) {
    float v[NCAND];
    int id[NCAND];
#pragma unroll
    for (int cc = 0; cc < NCAND; cc++) { v[cc] = resc[cc]; id[cc] = cand[cc]; }
    for (int a = 0; a < TOPK; a++) {
      int best = a;
      for (int b2 = a + 1; b2 < NCAND; b2++) {
        if (v[b2] > v[best] || (v[b2] == v[best] && id[b2] < id[best])) best = b2;
      }
      const float tv = v[a]; v[a] = v[best]; v[best] = tv;
      const int ti2 = id[a]; id[a] = id[best]; id[best] = ti2;
    }
    // Emulated softmax over top-16: serial ascending sum
    const float mx = v[0];
    float e[TOPK];
    float s = 0.f;
#pragma unroll
    for (int kk = 0; kk < TOPK; kk++) {
      e[kk] = exp_acc(__fsub_rn(v[kk], mx));
      s = __fadd_rn(s, e[kk]);
    }
#pragma unroll
    for (int kk = 0; kk < TOPK; kk++) {
      topi[kk] = id[kk];
      wts[kk] = __fdiv_rn(e[kk], s);
    }
  }
  __syncthreads();

  // ---- Outputs ----
  if (tid < TOPK) {
    out_idx[t * TOPK + tid] = (float)topi[tid];
    out_w[t * TOPK + tid] = wts[tid];
    out_sel[(size_t)t * NNEUR + topi[tid]] = wts[tid];
  }
  for (int d = tid; d < Dn; d += 256) {
    float a = 0.f;
#pragma unroll
    for (int kk = 0; kk < TOPK; kk++)   // serial ascending k (einsum order)
      a = __fmaf_rn(wts[kk], neurons[(size_t)topi[kk] * Dn + d], a);
    out_y[(size_t)t * Dn + d] = a;
  }
}

// ---------------------------------------------------------------------------
// Launch
// ---------------------------------------------------------------------------
extern "C" void kernel_launch(void* const* d_in, const int* in_sizes, int n_in,
                              void* d_out, int out_size) {
  (void)in_sizes; (void)n_in; (void)out_size;
  const float* x       = (const float*)d_in[0];
  const float* neurons = (const float*)d_in[1];
  const float* q_w     = (const float*)d_in[2];
  const float* q_b     = (const float*)d_in[3];
  const float* k_w     = (const float*)d_in[4];
  const float* k_b     = (const float*)d_in[5];
  const float* v_w     = (const float*)d_in[6];
  const float* v_b     = (const float*)d_in[7];
  const float* path_w  = (const float*)d_in[8];
  const float* path_b  = (const float*)d_in[9];
  float* out = (float*)d_out;

  float *gq, *gk, *gv, *gctx, *gy, *ggate, *gbig;
  cudaGetSymbolAddress((void**)&gq, g_q);
  cudaGetSymbolAddress((void**)&gk, g_k);
  cudaGetSymbolAddress((void**)&gv, g_v);
  cudaGetSymbolAddress((void**)&gctx, g_ctx);
  cudaGetSymbolAddress((void**)&gy, g_y);
  cudaGetSymbolAddress((void**)&ggate, g_gate);
  cudaGetSymbolAddress((void**)&gbig, g_big);

  // 1) QKV projections (serial-k fp32 SGEMM + fp32 bias add)
  dim3 qkv_grid(Dn / 128, MTOK / 128);  // (8, 32)
  sgemm128<false, true><<<qkv_grid, 256>>>(x, q_w, q_b, gq, MTOK, Dn, Dn);
  sgemm128<false, true><<<qkv_grid, 256>>>(x, k_w, k_b, gk, MTOK, Dn, Dn);
  sgemm128<false, true><<<qkv_grid, 256>>>(x, v_w, v_b, gv, MTOK, Dn, Dn);

  // 2) Attention: serial logits -> serial-sum softmax -> serial AV
  attn_logits_kernel<<<dim3(Sn / 64, Sn / 64, Bn * Hn), 128>>>(gq, gk, gbig);
  softmax_serial<<<(Bn * Hn * Sn) / 8, 256>>>(gbig);
  attn_av_kernel<<<dim3(Sn / 64, Bn * Hn), 128>>>(gbig, gv, gctx);

  // 3) Serial gate (stored) + fused y for the coarse GEMM
  gate_combine_serial<<<MTOK, 256>>>(x, gctx, path_w, path_b, gy, ggate);

  // 4) Coarse scores (fast fp32; candidate selection only)
  sgemm128<true, false><<<dim3(NNEUR / 128, MTOK / 128), 256>>>(
      gy, neurons, nullptr, gbig, MTOK, NNEUR, Dn);

  // 5) Candidates -> serial-emulated rescore -> top-16 -> outputs
  const size_t off_idx = (size_t)MTOK * Dn;
  const size_t off_w   = off_idx + (size_t)MTOK * TOPK;
  const size_t off_sel = off_w + (size_t)MTOK * TOPK;
  cudaMemsetAsync(out + off_sel, 0, (size_t)MTOK * NNEUR * sizeof(float));
  refine_topk_kernel<<<MTOK, 256>>>(gbig, x, gctx, neurons, ggate,
                                    out, out + off_idx, out + off_w,
                                    out + off_sel);
}

// round 10
// speedup vs baseline: 1.7144x; 1.7144x over previous
#include <cuda_runtime.h>
#include <cuda_bf16.h>
#include <mma.h>
#include <math.h>
#include <stdint.h>

using namespace nvcuda;

// Problem constants
#define Bn   4
#define Sn   1024
#define Dn   1024
#define Hn   16
#define DHn  64
#define NNEUR 16384
#define TOPK 16
#define NCAND 48
#define MTOK (Bn * Sn)   // 4096 tokens

// ---------------------------------------------------------------------------
// Scratch (device globals; no cudaMalloc allowed)
// ---------------------------------------------------------------------------
__device__ float g_q[MTOK * Dn];
__device__ float g_k[MTOK * Dn];
__device__ float g_v[MTOK * Dn];
__device__ float g_ctx[MTOK * Dn];
__device__ float g_gate[MTOK * 2];
__device__ __nv_bfloat16 g_yb[MTOK * Dn];           // bf16 gated combo (coarse only)
__device__ __nv_bfloat16 g_nb[(size_t)NNEUR * Dn];  // bf16 neurons (coarse only)
// Reused: attention logits [B*H, S, S] (67.1M) then coarse scores [B*S, N]
__device__ float g_big[(size_t)MTOK * NNEUR];

// ---------------------------------------------------------------------------
// Accurate expf (~1-2 ulp), independent of -use_fast_math (never calls expf).
// ---------------------------------------------------------------------------
__device__ __forceinline__ float exp_acc(float x) {
  if (x < -87.3f) return 0.0f;
  float t = __fmaf_rn(x, 1.44269504088896340736f, 12582912.0f);
  float k = __fsub_rn(t, 12582912.0f);           // round-to-nearest(x*log2e)
  float r = __fmaf_rn(k, -0.693359375f, x);      // Cody-Waite hi
  r = __fmaf_rn(k, 2.12194440e-4f, r);           // Cody-Waite lo
  float p = 1.9841269841269841e-4f;              // 1/5040
  p = __fmaf_rn(p, r, 1.3888888888888889e-3f);   // 1/720
  p = __fmaf_rn(p, r, 8.3333333333333333e-3f);   // 1/120
  p = __fmaf_rn(p, r, 4.1666666666666664e-2f);   // 1/24
  p = __fmaf_rn(p, r, 1.6666666666666666e-1f);   // 1/6
  p = __fmaf_rn(p, r, 0.5f);
  p = __fmaf_rn(p, r, 1.0f);
  p = __fmaf_rn(p, r, 1.0f);
  return ldexpf(p, (int)k);
}

// ---------------------------------------------------------------------------
// SGEMM, serial-ascending-k single-accumulator FMA (rank-critical stages;
// DO NOT change accumulation order). 128x128 tile, K-tile 8, 256 threads.
// ---------------------------------------------------------------------------
template <bool BT, bool BIAS>
__global__ __launch_bounds__(256, 2) void sgemm128(
    const float* __restrict__ A, const float* __restrict__ Bm,
    const float* __restrict__ bias, float* __restrict__ C,
    int M, int N, int K) {
  __shared__ float As[8][128];
  __shared__ float Bs[8][128];
  const int tid = threadIdx.x;
  const int m0 = blockIdx.y * 128;
  const int n0 = blockIdx.x * 128;
  const int ty = tid >> 4;   // 0..15
  const int tx = tid & 15;   // 0..15

  float acc[8][8];
#pragma unroll
  for (int i = 0; i < 8; i++)
#pragma unroll
    for (int j = 0; j < 8; j++) acc[i][j] = 0.f;

  const int lrow = tid >> 1;        // 0..127
  const int lcol = (tid & 1) * 4;   // 0 or 4
  const int krow = tid >> 5;        // 0..7
  const int kcol = (tid & 31) * 4;  // 0..124

  for (int k0 = 0; k0 < K; k0 += 8) {
    float4 av = *(const float4*)(A + (size_t)(m0 + lrow) * K + k0 + lcol);
    As[lcol + 0][lrow] = av.x;
    As[lcol + 1][lrow] = av.y;
    As[lcol + 2][lrow] = av.z;
    As[lcol + 3][lrow] = av.w;
    if (BT) {
      float4 bv = *(const float4*)(Bm + (size_t)(n0 + lrow) * K + k0 + lcol);
      Bs[lcol + 0][lrow] = bv.x;
      Bs[lcol + 1][lrow] = bv.y;
      Bs[lcol + 2][lrow] = bv.z;
      Bs[lcol + 3][lrow] = bv.w;
    } else {
      float4 bv = *(const float4*)(Bm + (size_t)(k0 + krow) * N + n0 + kcol);
      *(float4*)&Bs[krow][kcol] = bv;
    }
    __syncthreads();
#pragma unroll
    for (int kk = 0; kk < 8; kk++) {   // ascending k, serial accumulator
      float a[8], b[8];
      *(float4*)(a)     = *(const float4*)&As[kk][ty * 8];
      *(float4*)(a + 4) = *(const float4*)&As[kk][ty * 8 + 4];
      *(float4*)(b)     = *(const float4*)&Bs[kk][tx * 8];
      *(float4*)(b + 4) = *(const float4*)&Bs[kk][tx * 8 + 4];
#pragma unroll
      for (int i = 0; i < 8; i++)
#pragma unroll
        for (int j = 0; j < 8; j++)
          acc[i][j] = __fmaf_rn(a[i], b[j], acc[i][j]);
    }
    __syncthreads();
  }

  float bj[8];
#pragma unroll
  for (int j = 0; j < 8; j++) bj[j] = BIAS ? bias[n0 + tx * 8 + j] : 0.f;

#pragma unroll
  for (int i = 0; i < 8; i++) {
    const int row = m0 + ty * 8 + i;
    float* cp = C + (size_t)row * N + n0 + tx * 8;
    float4 o0 = make_float4(__fadd_rn(acc[i][0], bj[0]), __fadd_rn(acc[i][1], bj[1]),
                            __fadd_rn(acc[i][2], bj[2]), __fadd_rn(acc[i][3], bj[3]));
    float4 o1 = make_float4(__fadd_rn(acc[i][4], bj[4]), __fadd_rn(acc[i][5], bj[5]),
                            __fadd_rn(acc[i][6], bj[6]), __fadd_rn(acc[i][7], bj[7]));
    *(float4*)(cp) = o0;
    *(float4*)(cp + 4) = o1;
  }
}

// ---------------------------------------------------------------------------
// Attention logits: L[sq,sk] = fl(serial ascending d: Q.K) * 0.125
// ---------------------------------------------------------------------------
__global__ __launch_bounds__(128) void attn_logits_kernel(
    const float* __restrict__ q, const float* __restrict__ k,
    float* __restrict__ logits) {
  const int bh = blockIdx.z;
  const int b = bh >> 4, h = bh & 15;
  const int sq0 = blockIdx.y * 64;
  const int sk0 = blockIdx.x * 64;
  __shared__ float Qs[64][65];
  __shared__ float Ks[64][65];
  const int tid = threadIdx.x;

  for (int i = tid; i < 64 * 16; i += 128) {
    const int r = i >> 4;
    const int c = (i & 15) * 4;
    float4 vq = *(const float4*)(q + (size_t)(b * Sn + sq0 + r) * Dn + h * DHn + c);
    Qs[r][c] = vq.x; Qs[r][c + 1] = vq.y; Qs[r][c + 2] = vq.z; Qs[r][c + 3] = vq.w;
    float4 vk = *(const float4*)(k + (size_t)(b * Sn + sk0 + r) * Dn + h * DHn + c);
    Ks[r][c] = vk.x; Ks[r][c + 1] = vk.y; Ks[r][c + 2] = vk.z; Ks[r][c + 3] = vk.w;
  }
  __syncthreads();

  const int ty = tid >> 4;  // 0..7 -> 8 rows each
  const int tx = tid & 15;  // 0..15 -> 4 cols each
  float acc[8][4] = {};
  for (int kk = 0; kk < 64; kk++) {   // ascending d, serial
    float a[8], bb[4];
#pragma unroll
    for (int i = 0; i < 8; i++) a[i] = Qs[ty * 8 + i][kk];
#pragma unroll
    for (int j = 0; j < 4; j++) bb[j] = Ks[tx * 4 + j][kk];
#pragma unroll
    for (int i = 0; i < 8; i++)
#pragma unroll
      for (int j = 0; j < 4; j++) acc[i][j] = __fmaf_rn(a[i], bb[j], acc[i][j]);
  }

#pragma unroll
  for (int i = 0; i < 8; i++) {
    float* lp = logits + ((size_t)bh * Sn + sq0 + ty * 8 + i) * Sn + sk0 + tx * 4;
#pragma unroll
    for (int j = 0; j < 4; j++)
      lp[j] = __fmul_rn(acc[i][j], 0.125f);   // /sqrt(64): exact pow2
  }
}

// ---------------------------------------------------------------------------
// Row softmax (length 1024): exact max, exp_acc, SERIAL ASCENDING sum by
// lane 0, correctly-rounded divide. One warp per row; 8 rows per block.
// ---------------------------------------------------------------------------
__global__ __launch_bounds__(256) void softmax_serial(float* __restrict__ data) {
  const int w = threadIdx.x >> 5;
  const int lane = threadIdx.x & 31;
  float* p = data + ((size_t)blockIdx.x * 8 + w) * 1024;
  __shared__ float buf[8][1024];
  __shared__ float ssum[8];

  float mx = -INFINITY;
  for (int d = lane; d < 1024; d += 32) {
    const float v = p[d];
    buf[w][d] = v;
    mx = fmaxf(mx, v);
  }
#pragma unroll
  for (int off = 16; off; off >>= 1)
    mx = fmaxf(mx, __shfl_xor_sync(0xffffffffu, mx, off));

  for (int d = lane; d < 1024; d += 32)
    buf[w][d] = exp_acc(__fsub_rn(buf[w][d], mx));
  __syncwarp();
  if (lane == 0) {
    float s = 0.f;
    for (int d = 0; d < 1024; d++) s = __fadd_rn(s, buf[w][d]);  // serial asc
    ssum[w] = s;
  }
  __syncwarp();
  const float S = ssum[w];
  for (int d = lane; d < 1024; d += 32)
    p[d] = __fdiv_rn(buf[w][d], S);
}

// ---------------------------------------------------------------------------
// context = attn @ V, serial ascending over sk (S=1024), fp32 FMA chain,
// written in [B, S, H*DH] layout.
// ---------------------------------------------------------------------------
__global__ __launch_bounds__(128) void attn_av_kernel(
    const float* __restrict__ pm, const float* __restrict__ v,
    float* __restrict__ ctx) {
  const int bh = blockIdx.y;
  const int b = bh >> 4, h = bh & 15;
  const int sq0 = blockIdx.x * 64;
  __shared__ float Ps[64][65];
  __shared__ float Vs[64][65];
  const int tid = threadIdx.x;
  const int ty = tid >> 4;
  const int tx = tid & 15;
  float acc[8][4] = {};

  for (int sk0 = 0; sk0 < Sn; sk0 += 64) {   // ascending sk tiles
    for (int i = tid; i < 64 * 16; i += 128) {
      const int r = i >> 4;
      const int c = (i & 15) * 4;
      float4 pv = *(const float4*)(pm + ((size_t)bh * Sn + sq0 + r) * Sn + sk0 + c);
      Ps[r][c] = pv.x; Ps[r][c + 1] = pv.y; Ps[r][c + 2] = pv.z; Ps[r][c + 3] = pv.w;
      float4 vv = *(const float4*)(v + (size_t)(b * Sn + sk0 + r) * Dn + h * DHn + c);
      Vs[r][c] = vv.x; Vs[r][c + 1] = vv.y; Vs[r][c + 2] = vv.z; Vs[r][c + 3] = vv.w;
    }
    __syncthreads();
    for (int kk = 0; kk < 64; kk++) {        // ascending within tile
      float a[8], bb[4];
#pragma unroll
      for (int i = 0; i < 8; i++) a[i] = Ps[ty * 8 + i][kk];
#pragma unroll
      for (int j = 0; j < 4; j++) bb[j] = Vs[kk][tx * 4 + j];
#pragma unroll
      for (int i = 0; i < 8; i++)
#pragma unroll
        for (int j = 0; j < 4; j++) acc[i][j] = __fmaf_rn(a[i], bb[j], acc[i][j]);
    }
    __syncthreads();
  }

#pragma unroll
  for (int i = 0; i < 8; i++) {
    float* cp = ctx + (size_t)(b * Sn + sq0 + ty * 8 + i) * Dn + h * DHn + tx * 4;
    *(float4*)cp = make_float4(acc[i][0], acc[i][1], acc[i][2], acc[i][3]);
  }
}

// ---------------------------------------------------------------------------
// Gate: logits via SERIAL ASCENDING fp32 FMA over the 2048-concat order,
// one thread per logit. Emulated 2-way softmax, stored; y written in bf16
// (feeds the coarse tensor-core GEMM only).
// ---------------------------------------------------------------------------
__global__ __launch_bounds__(256) void gate_combine_serial(
    const float* __restrict__ x, const float* __restrict__ ctx,
    const float* __restrict__ pw, const float* __restrict__ pb,
    __nv_bfloat16* __restrict__ yb, float* __restrict__ gate) {
  const int t = blockIdx.x;
  const int tid = threadIdx.x;
  __shared__ float xs[Dn];
  __shared__ float cs[Dn];
  __shared__ float lg[2];
  __shared__ float w01[2];

  const float* xr = x + (size_t)t * Dn;
  const float* cr = ctx + (size_t)t * Dn;
  for (int d = tid * 4; d < Dn; d += 256 * 4) {
    *(float4*)&xs[d] = *(const float4*)(xr + d);
    *(float4*)&cs[d] = *(const float4*)(cr + d);
  }
  __syncthreads();

  if (tid < 2) {
    const int col = tid;
    float l = 0.f;
    for (int d = 0; d < Dn; d++)                      // x part, ascending
      l = __fmaf_rn(xs[d], pw[2 * d + col], l);
    for (int d = 0; d < Dn; d++)                      // ctx part, ascending
      l = __fmaf_rn(cs[d], pw[2 * (Dn + d) + col], l);
    lg[col] = __fadd_rn(l, pb[col]);                  // +bias (elementwise op)
  }
  __syncthreads();
  if (tid == 0) {
    const float l0 = lg[0], l1 = lg[1];
    const float m = fmaxf(l0, l1);
    const float e0 = exp_acc(__fsub_rn(l0, m));
    const float e1 = exp_acc(__fsub_rn(l1, m));
    const float S = __fadd_rn(e0, e1);
    w01[0] = __fdiv_rn(e0, S);
    w01[1] = __fdiv_rn(e1, S);
    gate[2 * t] = w01[0];
    gate[2 * t + 1] = w01[1];
  }
  __syncthreads();
  const float w0 = w01[0], w1 = w01[1];
  for (int d = tid; d < Dn; d += 256)
    yb[(size_t)t * Dn + d] = __float2bfloat16(w0 * xs[d] + w1 * cs[d]);
}

// ---------------------------------------------------------------------------
// fp32 -> bf16 bulk convert (neurons; coarse path only)
// ---------------------------------------------------------------------------
__global__ __launch_bounds__(256) void convert_bf16_kernel(
    const float* __restrict__ src, __nv_bfloat16* __restrict__ dst, int n4) {
  const int i = blockIdx.x * 256 + threadIdx.x;
  if (i < n4) {
    float4 v = *(const float4*)(src + (size_t)i * 4);
    __nv_bfloat162 lo = __floats2bfloat162_rn(v.x, v.y);
    __nv_bfloat162 hi = __floats2bfloat162_rn(v.z, v.w);
    uint2 pk;
    pk.x = *(uint32_t*)&lo;
    pk.y = *(uint32_t*)&hi;
    *(uint2*)(dst + (size_t)i * 4) = pk;
  }
}

// ---------------------------------------------------------------------------
// Coarse scores on TENSOR CORES: C[M,N] = Y[M,K](bf16) @ Nr[N,K]^T(bf16),
// fp32 accumulate. Candidate nomination only — precision slack is proven.
// 128x128 block tile, 8 warps (each 32x64), K-chunk 32 via smem.
// ---------------------------------------------------------------------------
__global__ __launch_bounds__(256, 2) void bf16_gemm_coarse(
    const __nv_bfloat16* __restrict__ A,   // [M,K] row-major
    const __nv_bfloat16* __restrict__ B,   // [N,K] row-major (neurons)
    float* __restrict__ C, int M, int N, int K) {
  __shared__ __nv_bfloat16 As[128][40];   // pad 32->40 (80B rows, 16B aligned)
  __shared__ __nv_bfloat16 Bs[128][40];
  const int tid = threadIdx.x;
  const int warp = tid >> 5;
  const int m0 = blockIdx.y * 128;
  const int n0 = blockIdx.x * 128;
  const int wm = (warp >> 1) * 32;   // 0,32,64,96
  const int wn = (warp & 1) * 64;    // 0,64

  wmma::fragment<wmma::accumulator, 16, 16, 16, float> acc[2][4];
#pragma unroll
  for (int i = 0; i < 2; i++)
#pragma unroll
    for (int j = 0; j < 4; j++) wmma::fill_fragment(acc[i][j], 0.0f);

  const int lrow = tid >> 2;         // 0..63
  const int seg = (tid & 3) * 8;     // 0,8,16,24 (bf16 elements)

  for (int k0 = 0; k0 < K; k0 += 32) {
#pragma unroll
    for (int p = 0; p < 2; p++) {
      const int r = lrow + p * 64;
      *(uint4*)&As[r][seg] = *(const uint4*)(A + (size_t)(m0 + r) * K + k0 + seg);
      *(uint4*)&Bs[r][seg] = *(const uint4*)(B + (size_t)(n0 + r) * K + k0 + seg);
    }
    __syncthreads();
#pragma unroll
    for (int ks = 0; ks < 32; ks += 16) {
      wmma::fragment<wmma::matrix_a, 16, 16, 16, __nv_bfloat16, wmma::row_major> fa[2];
      wmma::fragment<wmma::matrix_b, 16, 16, 16, __nv_bfloat16, wmma::col_major> fb[4];
#pragma unroll
      for (int i = 0; i < 2; i++)
        wmma::load_matrix_sync(fa[i], &As[wm + i * 16][ks], 40);
#pragma unroll
      for (int j = 0; j < 4; j++)
        wmma::load_matrix_sync(fb[j], &Bs[wn + j * 16][ks], 40);
#pragma unroll
      for (int i = 0; i < 2; i++)
#pragma unroll
        for (int j = 0; j < 4; j++)
          wmma::mma_sync(acc[i][j], fa[i], fb[j], acc[i][j]);
    }
    __syncthreads();
  }

#pragma unroll
  for (int i = 0; i < 2; i++)
#pragma unroll
    for (int j = 0; j < 4; j++)
      wmma::store_matrix_sync(C + (size_t)(m0 + wm + i * 16) * N + n0 + wn + j * 16,
                              acc[i][j], N, wmma::mem_row_major);
}

// ---------------------------------------------------------------------------
// Candidate top-48 (coarse) -> SERIAL fp32 rescore (Eigen-order) ->
// top-16 with jax tie-break -> emulated softmax -> outputs.
// (Unchanged from R9 — rank-critical, proven correct.)
// ---------------------------------------------------------------------------
__global__ __launch_bounds__(256) void refine_topk_kernel(
    const float* __restrict__ coarse, const float* __restrict__ x,
    const float* __restrict__ ctx, const float* __restrict__ neurons,
    const float* __restrict__ gate,
    float* __restrict__ out_y, float* __restrict__ out_idx,
    float* __restrict__ out_w, float* __restrict__ out_sel) {
  const int t = blockIdx.x;
  const int tid = threadIdx.x;
  const int lane = tid & 31;
  const int warp = tid >> 5;

  __shared__ float x_s[Dn];
  __shared__ float c_s[Dn];
  __shared__ float nbuf[8][Dn];     // 32KB: 8 staged neuron rows
  __shared__ float rv[256];
  __shared__ int ri[256];
  __shared__ int cand[NCAND];
  __shared__ float resc[NCAND];
  __shared__ float scratch[16];
  __shared__ int topi[TOPK];
  __shared__ float wts[TOPK];

  {
    const float* xr = x + (size_t)t * Dn;
    const float* cr = ctx + (size_t)t * Dn;
    for (int d = tid * 4; d < Dn; d += 256 * 4) {
      *(float4*)&x_s[d] = *(const float4*)(xr + d);
      *(float4*)&c_s[d] = *(const float4*)(cr + d);
    }
  }
  __syncthreads();

  // ---- Coarse top-NCAND candidate selection ----
  float sv[64];
  {
    const float* sr = coarse + (size_t)t * NNEUR;
#pragma unroll
    for (int j = 0; j < 64; j++) sv[j] = sr[j * 256 + tid];
  }
  float bv = -INFINITY;
  int bj = 0;
#pragma unroll
  for (int j = 0; j < 64; j++)
    if (sv[j] > bv) { bv = sv[j]; bj = j; }

  for (int r = 0; r < NCAND; r++) {
    rv[tid] = bv;
    ri[tid] = bj * 256 + tid;
    __syncthreads();
    for (int off = 128; off; off >>= 1) {
      if (tid < off) {
        const float v2 = rv[tid + off];
        const int i2 = ri[tid + off];
        if (v2 > rv[tid] || (v2 == rv[tid] && i2 < ri[tid])) {
          rv[tid] = v2; ri[tid] = i2;
        }
      }
      __syncthreads();
    }
    const int widx = ri[0];
    if (tid == 0) cand[r] = widx;
    if ((widx & 255) == tid) {
      sv[widx >> 8] = -INFINITY;
      bv = -INFINITY; bj = 0;
#pragma unroll
      for (int j = 0; j < 64; j++)
        if (sv[j] > bv) { bv = sv[j]; bj = j; }
    }
    __syncthreads();
  }

  // ---- Serial rescore: waves of 8 candidates ----
  const float w0 = gate[2 * t], w1 = gate[2 * t + 1];
  for (int wave = 0; wave < NCAND / 8; wave++) {
    const int ci = wave * 8 + warp;
    const float* nr = neurons + (size_t)cand[ci] * Dn;
    for (int d = lane * 4; d < Dn; d += 32 * 4)
      *(float4*)&nbuf[warp][d] = *(const float4*)(nr + d);
    __syncthreads();
    if (tid < 16) {
      const int c = tid >> 1;
      const float* vrow = (tid & 1) ? c_s : x_s;
      float acc = 0.f;
      for (int d = 0; d < Dn; d++)                 // serial ascending FMA
        acc = __fmaf_rn(vrow[d], nbuf[c][d], acc);
      scratch[tid] = acc;
    }
    __syncthreads();
    if (tid < 8) {
      const float tsr = scratch[2 * tid];          // fp32 token score
      const float csr = scratch[2 * tid + 1];      // fp32 context score
      resc[wave * 8 + tid] = __fadd_rn(__fmul_rn(w0, tsr), __fmul_rn(w1, csr));
    }
    __syncthreads();
  }

  // ---- Top-16 among NCAND: value desc, tie -> lower index ----
  if (tid == 0) {
    float v[NCAND];
    int id[NCAND];
#pragma unroll
    for (int cc = 0; cc < NCAND; cc++) { v[cc] = resc[cc]; id[cc] = cand[cc]; }
    for (int a = 0; a < TOPK; a++) {
      int best = a;
      for (int b2 = a + 1; b2 < NCAND; b2++) {
        if (v[b2] > v[best] || (v[b2] == v[best] && id[b2] < id[best])) best = b2;
      }
      const float tv = v[a]; v[a] = v[best]; v[best] = tv;
      const int ti2 = id[a]; id[a] = id[best]; id[best] = ti2;
    }
    // Emulated softmax over top-16: serial ascending sum
    const float mx = v[0];
    float e[TOPK];
    float s = 0.f;
#pragma unroll
    for (int kk = 0; kk < TOPK; kk++) {
      e[kk] = exp_acc(__fsub_rn(v[kk], mx));
      s = __fadd_rn(s, e[kk]);
    }
#pragma unroll
    for (int kk = 0; kk < TOPK; kk++) {
      topi[kk] = id[kk];
      wts[kk] = __fdiv_rn(e[kk], s);
    }
  }
  __syncthreads();

  // ---- Outputs ----
  if (tid < TOPK) {
    out_idx[t * TOPK + tid] = (float)topi[tid];
    out_w[t * TOPK + tid] = wts[tid];
    out_sel[(size_t)t * NNEUR + topi[tid]] = wts[tid];
  }
  for (int d = tid; d < Dn; d += 256) {
    float a = 0.f;
#pragma unroll
    for (int kk = 0; kk < TOPK; kk++)   // serial ascending k (einsum order)
      a = __fmaf_rn(wts[kk], neurons[(size_t)topi[kk] * Dn + d], a);
    out_y[(size_t)t * Dn + d] = a;
  }
}

// ---------------------------------------------------------------------------
// Launch
// ---------------------------------------------------------------------------
extern "C" void kernel_launch(void* const* d_in, const int* in_sizes, int n_in,
                              void* d_out, int out_size) {
  (void)in_sizes; (void)n_in; (void)out_size;
  const float* x       = (const float*)d_in[0];
  const float* neurons = (const float*)d_in[1];
  const float* q_w     = (const float*)d_in[2];
  const float* q_b     = (const float*)d_in[3];
  const float* k_w     = (const float*)d_in[4];
  const float* k_b     = (const float*)d_in[5];
  const float* v_w     = (const float*)d_in[6];
  const float* v_b     = (const float*)d_in[7];
  const float* path_w  = (const float*)d_in[8];
  const float* path_b  = (const float*)d_in[9];
  float* out = (float*)d_out;

  float *gq, *gk, *gv, *gctx, *ggate, *gbig;
  __nv_bfloat16 *gyb, *gnb;
  cudaGetSymbolAddress((void**)&gq, g_q);
  cudaGetSymbolAddress((void**)&gk, g_k);
  cudaGetSymbolAddress((void**)&gv, g_v);
  cudaGetSymbolAddress((void**)&gctx, g_ctx);
  cudaGetSymbolAddress((void**)&ggate, g_gate);
  cudaGetSymbolAddress((void**)&gbig, g_big);
  cudaGetSymbolAddress((void**)&gyb, g_yb);
  cudaGetSymbolAddress((void**)&gnb, g_nb);

  // 0) bf16 neurons for the coarse tensor-core GEMM (overlaps QKV on GPU)
  const int n4 = (NNEUR * Dn) / 4;
  convert_bf16_kernel<<<(n4 + 255) / 256, 256>>>(neurons, gnb, n4);

  // 1) QKV projections (serial-k fp32 SGEMM + fp32 bias add) — rank-critical
  dim3 qkv_grid(Dn / 128, MTOK / 128);  // (8, 32)
  sgemm128<false, true><<<qkv_grid, 256>>>(x, q_w, q_b, gq, MTOK, Dn, Dn);
  sgemm128<false, true><<<qkv_grid, 256>>>(x, k_w, k_b, gk, MTOK, Dn, Dn);
  sgemm128<false, true><<<qkv_grid, 256>>>(x, v_w, v_b, gv, MTOK, Dn, Dn);

  // 2) Attention: serial logits -> serial-sum softmax -> serial AV
  attn_logits_kernel<<<dim3(Sn / 64, Sn / 64, Bn * Hn), 128>>>(gq, gk, gbig);
  softmax_serial<<<(Bn * Hn * Sn) / 8, 256>>>(gbig);
  attn_av_kernel<<<dim3(Sn / 64, Bn * Hn), 128>>>(gbig, gv, gctx);

  // 3) Serial gate (stored) + bf16 y for the coarse GEMM
  gate_combine_serial<<<MTOK, 256>>>(x, gctx, path_w, path_b, gyb, ggate);

  // 4) Coarse scores on tensor cores (bf16 in, fp32 accum; nomination only)
  bf16_gemm_coarse<<<dim3(NNEUR / 128, MTOK / 128), 256>>>(
      gyb, gnb, gbig, MTOK, NNEUR, Dn);

  // 5) Candidates -> serial-emulated rescore -> top-16 -> outputs
  const size_t off_idx = (size_t)MTOK * Dn;
  const size_t off_w   = off_idx + (size_t)MTOK * TOPK;
  const size_t off_sel = off_w + (size_t)MTOK * TOPK;
  cudaMemsetAsync(out + off_sel, 0, (size_t)MTOK * NNEUR * sizeof(float));
  refine_topk_kernel<<<MTOK, 256>>>(gbig, x, gctx, neurons, ggate,
                                    out, out + off_idx, out + off_w,
                                    out + off_sel);
}

// round 11
// speedup vs baseline: 1.9498x; 1.1373x over previous
#include <cuda_runtime.h>
#include <cuda_bf16.h>
#include <cuda_pipeline.h>
#include <mma.h>
#include <math.h>
#include <stdint.h>

using namespace nvcuda;

// Problem constants
#define Bn   4
#define Sn   1024
#define Dn   1024
#define Hn   16
#define DHn  64
#define NNEUR 16384
#define TOPK 16
#define NCAND 48
#define MTOK (Bn * Sn)   // 4096 tokens

// ---------------------------------------------------------------------------
// Scratch (device globals; no cudaMalloc allowed)
// ---------------------------------------------------------------------------
__device__ float g_q[MTOK * Dn];
__device__ float g_k[MTOK * Dn];
__device__ float g_v[MTOK * Dn];
__device__ float g_ctx[MTOK * Dn];
__device__ float g_gate[MTOK * 2];
__device__ __nv_bfloat16 g_yb[MTOK * Dn];           // bf16 gated combo (coarse only)
__device__ __nv_bfloat16 g_nb[(size_t)NNEUR * Dn];  // bf16 neurons (coarse only)
// Reused: attention logits [B*H, S, S] (67.1M) then coarse scores [B*S, N]
__device__ float g_big[(size_t)MTOK * NNEUR];

// ---------------------------------------------------------------------------
// Accurate expf (~1-2 ulp), independent of -use_fast_math (never calls expf).
// ---------------------------------------------------------------------------
__device__ __forceinline__ float exp_acc(float x) {
  if (x < -87.3f) return 0.0f;
  float t = __fmaf_rn(x, 1.44269504088896340736f, 12582912.0f);
  float k = __fsub_rn(t, 12582912.0f);           // round-to-nearest(x*log2e)
  float r = __fmaf_rn(k, -0.693359375f, x);      // Cody-Waite hi
  r = __fmaf_rn(k, 2.12194440e-4f, r);           // Cody-Waite lo
  float p = 1.9841269841269841e-4f;              // 1/5040
  p = __fmaf_rn(p, r, 1.3888888888888889e-3f);   // 1/720
  p = __fmaf_rn(p, r, 8.3333333333333333e-3f);   // 1/120
  p = __fmaf_rn(p, r, 4.1666666666666664e-2f);   // 1/24
  p = __fmaf_rn(p, r, 1.6666666666666666e-1f);   // 1/6
  p = __fmaf_rn(p, r, 0.5f);
  p = __fmaf_rn(p, r, 1.0f);
  p = __fmaf_rn(p, r, 1.0f);
  return ldexpf(p, (int)k);
}

// ---------------------------------------------------------------------------
// SGEMM, serial-ascending-k single-accumulator FMA per output element
// (rank-critical; accumulation order MUST NOT change). 128x128 tile, K-tile 8,
// 256 threads. Register-prefetch double buffering (value-identical).
// BT=false: C = A[M,K] @ B[K,N]; BT=true: C = A[M,K] @ B[N,K]^T.
// ---------------------------------------------------------------------------
template <bool BT, bool BIAS>
__global__ __launch_bounds__(256, 2) void sgemm128(
    const float* __restrict__ A, const float* __restrict__ Bm,
    const float* __restrict__ bias, float* __restrict__ C,
    int M, int N, int K) {
  __shared__ float As[8][128];
  __shared__ float Bs[8][128];
  const int tid = threadIdx.x;
  const int m0 = blockIdx.y * 128;
  const int n0 = blockIdx.x * 128;
  const int ty = tid >> 4;   // 0..15
  const int tx = tid & 15;   // 0..15

  float acc[8][8];
#pragma unroll
  for (int i = 0; i < 8; i++)
#pragma unroll
    for (int j = 0; j < 8; j++) acc[i][j] = 0.f;

  const int lrow = tid >> 1;        // 0..127
  const int lcol = (tid & 1) * 4;   // 0 or 4
  const int krow = tid >> 5;        // 0..7
  const int kcol = (tid & 31) * 4;  // 0..124

  // prefetch tile k0=0
  float4 pa = *(const float4*)(A + (size_t)(m0 + lrow) * K + lcol);
  float4 pb;
  if (BT) pb = *(const float4*)(Bm + (size_t)(n0 + lrow) * K + lcol);
  else    pb = *(const float4*)(Bm + (size_t)krow * N + n0 + kcol);

  for (int k0 = 0; k0 < K; k0 += 8) {
    As[lcol + 0][lrow] = pa.x;
    As[lcol + 1][lrow] = pa.y;
    As[lcol + 2][lrow] = pa.z;
    As[lcol + 3][lrow] = pa.w;
    if (BT) {
      Bs[lcol + 0][lrow] = pb.x;
      Bs[lcol + 1][lrow] = pb.y;
      Bs[lcol + 2][lrow] = pb.z;
      Bs[lcol + 3][lrow] = pb.w;
    } else {
      *(float4*)&Bs[krow][kcol] = pb;
    }
    __syncthreads();
    if (k0 + 8 < K) {   // prefetch next tile (overlaps compute)
      pa = *(const float4*)(A + (size_t)(m0 + lrow) * K + k0 + 8 + lcol);
      if (BT) pb = *(const float4*)(Bm + (size_t)(n0 + lrow) * K + k0 + 8 + lcol);
      else    pb = *(const float4*)(Bm + (size_t)(k0 + 8 + krow) * N + n0 + kcol);
    }
#pragma unroll
    for (int kk = 0; kk < 8; kk++) {   // ascending k, serial accumulator
      float a[8], b[8];
      *(float4*)(a)     = *(const float4*)&As[kk][ty * 8];
      *(float4*)(a + 4) = *(const float4*)&As[kk][ty * 8 + 4];
      *(float4*)(b)     = *(const float4*)&Bs[kk][tx * 8];
      *(float4*)(b + 4) = *(const float4*)&Bs[kk][tx * 8 + 4];
#pragma unroll
      for (int i = 0; i < 8; i++)
#pragma unroll
        for (int j = 0; j < 8; j++)
          acc[i][j] = __fmaf_rn(a[i], b[j], acc[i][j]);
    }
    __syncthreads();
  }

  float bj[8];
#pragma unroll
  for (int j = 0; j < 8; j++) bj[j] = BIAS ? bias[n0 + tx * 8 + j] : 0.f;

#pragma unroll
  for (int i = 0; i < 8; i++) {
    const int row = m0 + ty * 8 + i;
    float* cp = C + (size_t)row * N + n0 + tx * 8;
    float4 o0 = make_float4(__fadd_rn(acc[i][0], bj[0]), __fadd_rn(acc[i][1], bj[1]),
                            __fadd_rn(acc[i][2], bj[2]), __fadd_rn(acc[i][3], bj[3]));
    float4 o1 = make_float4(__fadd_rn(acc[i][4], bj[4]), __fadd_rn(acc[i][5], bj[5]),
                            __fadd_rn(acc[i][6], bj[6]), __fadd_rn(acc[i][7], bj[7]));
    *(float4*)(cp) = o0;
    *(float4*)(cp + 4) = o1;
  }
}

// ---------------------------------------------------------------------------
// Attention logits v2: sgemm-style 128x128 tile, transposed smem (vector LDS).
// Per (b,h): L[sq,sk] = fl(serial ascending d: Q.K) * 0.125 — values
// bit-identical to v1 (same ascending-d single-accumulator chain).
// Dynamic smem: 2 * 64 * 132 * 4 = 67,584 B.
// ---------------------------------------------------------------------------
#define LOG2_SMEM (2 * 64 * 132 * 4)
__global__ __launch_bounds__(256, 2) void attn_logits_v2(
    const float* __restrict__ q, const float* __restrict__ k,
    float* __restrict__ logits) {
  extern __shared__ float sm_l[];
  float (*Qs)[132] = (float(*)[132])sm_l;
  float (*Ks)[132] = (float(*)[132])(sm_l + 64 * 132);
  const int bh = blockIdx.z;
  const int b = bh >> 4, h = bh & 15;
  const int m0 = blockIdx.y * 128;
  const int n0 = blockIdx.x * 128;
  const int tid = threadIdx.x;

  {
    const int row = tid >> 1;          // 0..127
    const int fbase = (tid & 1) * 8;   // float4 group 0 or 8
    const float* qb = q + (size_t)(b * Sn + m0 + row) * Dn + h * DHn;
    const float* kb = k + (size_t)(b * Sn + n0 + row) * Dn + h * DHn;
#pragma unroll
    for (int f = 0; f < 8; f++) {
      const int c = (fbase + f) * 4;
      float4 vq = *(const float4*)(qb + c);
      float4 vk = *(const float4*)(kb + c);
      Qs[c + 0][row] = vq.x; Qs[c + 1][row] = vq.y;
      Qs[c + 2][row] = vq.z; Qs[c + 3][row] = vq.w;
      Ks[c + 0][row] = vk.x; Ks[c + 1][row] = vk.y;
      Ks[c + 2][row] = vk.z; Ks[c + 3][row] = vk.w;
    }
  }
  __syncthreads();

  const int ty = tid >> 4;   // 0..15 -> 8 rows
  const int tx = tid & 15;   // 0..15 -> 8 cols
  float acc[8][8];
#pragma unroll
  for (int i = 0; i < 8; i++)
#pragma unroll
    for (int j = 0; j < 8; j++) acc[i][j] = 0.f;

  for (int kk = 0; kk < 64; kk++) {   // ascending d, serial accumulator
    float a[8], bb[8];
    *(float4*)(a)      = *(const float4*)&Qs[kk][ty * 8];
    *(float4*)(a + 4)  = *(const float4*)&Qs[kk][ty * 8 + 4];
    *(float4*)(bb)     = *(const float4*)&Ks[kk][tx * 8];
    *(float4*)(bb + 4) = *(const float4*)&Ks[kk][tx * 8 + 4];
#pragma unroll
    for (int i = 0; i < 8; i++)
#pragma unroll
      for (int j = 0; j < 8; j++)
        acc[i][j] = __fmaf_rn(a[i], bb[j], acc[i][j]);
  }

#pragma unroll
  for (int i = 0; i < 8; i++) {
    float* lp = logits + ((size_t)bh * Sn + m0 + ty * 8 + i) * Sn + n0 + tx * 8;
    float4 o0 = make_float4(__fmul_rn(acc[i][0], 0.125f), __fmul_rn(acc[i][1], 0.125f),
                            __fmul_rn(acc[i][2], 0.125f), __fmul_rn(acc[i][3], 0.125f));
    float4 o1 = make_float4(__fmul_rn(acc[i][4], 0.125f), __fmul_rn(acc[i][5], 0.125f),
                            __fmul_rn(acc[i][6], 0.125f), __fmul_rn(acc[i][7], 0.125f));
    *(float4*)(lp) = o0;
    *(float4*)(lp + 4) = o1;
  }
}

// ---------------------------------------------------------------------------
// Row softmax (length 1024): exact max, exp_acc, SERIAL ASCENDING sum by
// lane 0, correctly-rounded divide. One warp per row; 8 rows per block.
// ---------------------------------------------------------------------------
__global__ __launch_bounds__(256) void softmax_serial(float* __restrict__ data) {
  const int w = threadIdx.x >> 5;
  const int lane = threadIdx.x & 31;
  float* p = data + ((size_t)blockIdx.x * 8 + w) * 1024;
  __shared__ float buf[8][1024];
  __shared__ float ssum[8];

  float mx = -INFINITY;
  for (int d = lane; d < 1024; d += 32) {
    const float v = p[d];
    buf[w][d] = v;
    mx = fmaxf(mx, v);
  }
#pragma unroll
  for (int off = 16; off; off >>= 1)
    mx = fmaxf(mx, __shfl_xor_sync(0xffffffffu, mx, off));

  for (int d = lane; d < 1024; d += 32)
    buf[w][d] = exp_acc(__fsub_rn(buf[w][d], mx));
  __syncwarp();
  if (lane == 0) {
    float s = 0.f;
    for (int d = 0; d < 1024; d++) s = __fadd_rn(s, buf[w][d]);  // serial asc
    ssum[w] = s;
  }
  __syncwarp();
  const float S = ssum[w];
  for (int d = lane; d < 1024; d += 32)
    p[d] = __fdiv_rn(buf[w][d], S);
}

// ---------------------------------------------------------------------------
// context = attn @ V, serial ascending over sk (S=1024), fp32 FMA chain,
// written in [B, S, H*DH] layout.
// ---------------------------------------------------------------------------
__global__ __launch_bounds__(128) void attn_av_kernel(
    const float* __restrict__ pm, const float* __restrict__ v,
    float* __restrict__ ctx) {
  const int bh = blockIdx.y;
  const int b = bh >> 4, h = bh & 15;
  const int sq0 = blockIdx.x * 64;
  __shared__ float Ps[64][65];
  __shared__ float Vs[64][65];
  const int tid = threadIdx.x;
  const int ty = tid >> 4;
  const int tx = tid & 15;
  float acc[8][4] = {};

  for (int sk0 = 0; sk0 < Sn; sk0 += 64) {   // ascending sk tiles
    for (int i = tid; i < 64 * 16; i += 128) {
      const int r = i >> 4;
      const int c = (i & 15) * 4;
      float4 pv = *(const float4*)(pm + ((size_t)bh * Sn + sq0 + r) * Sn + sk0 + c);
      Ps[r][c] = pv.x; Ps[r][c + 1] = pv.y; Ps[r][c + 2] = pv.z; Ps[r][c + 3] = pv.w;
      float4 vv = *(const float4*)(v + (size_t)(b * Sn + sk0 + r) * Dn + h * DHn + c);
      Vs[r][c] = vv.x; Vs[r][c + 1] = vv.y; Vs[r][c + 2] = vv.z; Vs[r][c + 3] = vv.w;
    }
    __syncthreads();
    for (int kk = 0; kk < 64; kk++) {        // ascending within tile
      float a[8], bb[4];
#pragma unroll
      for (int i = 0; i < 8; i++) a[i] = Ps[ty * 8 + i][kk];
#pragma unroll
      for (int j = 0; j < 4; j++) bb[j] = Vs[kk][tx * 4 + j];
#pragma unroll
      for (int i = 0; i < 8; i++)
#pragma unroll
        for (int j = 0; j < 4; j++) acc[i][j] = __fmaf_rn(a[i], bb[j], acc[i][j]);
    }
    __syncthreads();
  }

#pragma unroll
  for (int i = 0; i < 8; i++) {
    float* cp = ctx + (size_t)(b * Sn + sq0 + ty * 8 + i) * Dn + h * DHn + tx * 4;
    *(float4*)cp = make_float4(acc[i][0], acc[i][1], acc[i][2], acc[i][3]);
  }
}

// ---------------------------------------------------------------------------
// Gate: logits via SERIAL ASCENDING fp32 FMA over the 2048-concat order,
// one thread per logit. Emulated 2-way softmax, stored; y written in bf16
// (feeds the coarse tensor-core GEMM only).
// ---------------------------------------------------------------------------
__global__ __launch_bounds__(256) void gate_combine_serial(
    const float* __restrict__ x, const float* __restrict__ ctx,
    const float* __restrict__ pw, const float* __restrict__ pb,
    __nv_bfloat16* __restrict__ yb, float* __restrict__ gate) {
  const int t = blockIdx.x;
  const int tid = threadIdx.x;
  __shared__ float xs[Dn];
  __shared__ float cs[Dn];
  __shared__ float lg[2];
  __shared__ float w01[2];

  const float* xr = x + (size_t)t * Dn;
  const float* cr = ctx + (size_t)t * Dn;
  for (int d = tid * 4; d < Dn; d += 256 * 4) {
    *(float4*)&xs[d] = *(const float4*)(xr + d);
    *(float4*)&cs[d] = *(const float4*)(cr + d);
  }
  __syncthreads();

  if (tid < 2) {
    const int col = tid;
    float l = 0.f;
    for (int d = 0; d < Dn; d++)                      // x part, ascending
      l = __fmaf_rn(xs[d], pw[2 * d + col], l);
    for (int d = 0; d < Dn; d++)                      // ctx part, ascending
      l = __fmaf_rn(cs[d], pw[2 * (Dn + d) + col], l);
    lg[col] = __fadd_rn(l, pb[col]);                  // +bias (elementwise op)
  }
  __syncthreads();
  if (tid == 0) {
    const float l0 = lg[0], l1 = lg[1];
    const float m = fmaxf(l0, l1);
    const float e0 = exp_acc(__fsub_rn(l0, m));
    const float e1 = exp_acc(__fsub_rn(l1, m));
    const float S = __fadd_rn(e0, e1);
    w01[0] = __fdiv_rn(e0, S);
    w01[1] = __fdiv_rn(e1, S);
    gate[2 * t] = w01[0];
    gate[2 * t + 1] = w01[1];
  }
  __syncthreads();
  const float w0 = w01[0], w1 = w01[1];
  for (int d = tid; d < Dn; d += 256)
    yb[(size_t)t * Dn + d] = __float2bfloat16(w0 * xs[d] + w1 * cs[d]);
}

// ---------------------------------------------------------------------------
// fp32 -> bf16 bulk convert (neurons; coarse path only)
// ---------------------------------------------------------------------------
__global__ __launch_bounds__(256) void convert_bf16_kernel(
    const float* __restrict__ src, __nv_bfloat16* __restrict__ dst, int n4) {
  const int i = blockIdx.x * 256 + threadIdx.x;
  if (i < n4) {
    float4 v = *(const float4*)(src + (size_t)i * 4);
    __nv_bfloat162 lo = __floats2bfloat162_rn(v.x, v.y);
    __nv_bfloat162 hi = __floats2bfloat162_rn(v.z, v.w);
    uint2 pk;
    pk.x = *(uint32_t*)&lo;
    pk.y = *(uint32_t*)&hi;
    *(uint2*)(dst + (size_t)i * 4) = pk;
  }
}

// ---------------------------------------------------------------------------
// Coarse scores on TENSOR CORES v2: cp.async 2-stage pipeline, K-chunk 64.
// C[M,N] = Y[M,K](bf16) @ Nr[N,K]^T(bf16), fp32 accum. Nomination only.
// Dynamic smem: 2 stages * (128x72 A + 128x72 B) bf16 = 73,728 B.
// ---------------------------------------------------------------------------
#define COARSE_SMEM (2 * 2 * 128 * 72 * 2)
__device__ __forceinline__ void coarse_issue(
    const __nv_bfloat16* __restrict__ A, const __nv_bfloat16* __restrict__ B,
    __nv_bfloat16 (*As)[72], __nv_bfloat16 (*Bs)[72],
    int s, int k0, int m0, int n0, int K, int tid) {
#pragma unroll
  for (int i = 0; i < 4; i++) {
    const int l = tid + 256 * i;
    const int r = l >> 3;
    const int c = (l & 7) * 8;
    __pipeline_memcpy_async(&As[s * 128 + r][c],
                            A + (size_t)(m0 + r) * K + k0 + c, 16);
    __pipeline_memcpy_async(&Bs[s * 128 + r][c],
                            B + (size_t)(n0 + r) * K + k0 + c, 16);
  }
  __pipeline_commit();
}

__global__ __launch_bounds__(256, 2) void bf16_gemm_coarse(
    const __nv_bfloat16* __restrict__ A,   // [M,K] row-major
    const __nv_bfloat16* __restrict__ B,   // [N,K] row-major (neurons)
    float* __restrict__ C, int M, int N, int K) {
  extern __shared__ __nv_bfloat16 smb[];
  __nv_bfloat16 (*As)[72] = (__nv_bfloat16(*)[72])smb;               // [256][72]
  __nv_bfloat16 (*Bs)[72] = (__nv_bfloat16(*)[72])(smb + 256 * 72);  // [256][72]
  const int tid = threadIdx.x;
  const int warp = tid >> 5;
  const int m0 = blockIdx.y * 128;
  const int n0 = blockIdx.x * 128;
  const int wm = (warp >> 1) * 32;   // 0,32,64,96
  const int wn = (warp & 1) * 64;    // 0,64

  wmma::fragment<wmma::accumulator, 16, 16, 16, float> acc[2][4];
#pragma unroll
  for (int i = 0; i < 2; i++)
#pragma unroll
    for (int j = 0; j < 4; j++) wmma::fill_fragment(acc[i][j], 0.0f);

  coarse_issue(A, B, As, Bs, 0, 0, m0, n0, K, tid);
  const int T = K / 64;   // 16
  for (int t = 0; t < T; t++) {
    if (t + 1 < T) coarse_issue(A, B, As, Bs, (t + 1) & 1, (t + 1) * 64, m0, n0, K, tid);
    if (t + 1 < T) __pipeline_wait_prior(1);
    else           __pipeline_wait_prior(0);
    __syncthreads();
    const int s = t & 1;
#pragma unroll
    for (int ks = 0; ks < 64; ks += 16) {
      wmma::fragment<wmma::matrix_a, 16, 16, 16, __nv_bfloat16, wmma::row_major> fa[2];
      wmma::fragment<wmma::matrix_b, 16, 16, 16, __nv_bfloat16, wmma::col_major> fb[4];
#pragma unroll
      for (int i = 0; i < 2; i++)
        wmma::load_matrix_sync(fa[i], &As[s * 128 + wm + i * 16][ks], 72);
#pragma unroll
      for (int j = 0; j < 4; j++)
        wmma::load_matrix_sync(fb[j], &Bs[s * 128 + wn + j * 16][ks], 72);
#pragma unroll
      for (int i = 0; i < 2; i++)
#pragma unroll
        for (int j = 0; j < 4; j++)
          wmma::mma_sync(acc[i][j], fa[i], fb[j], acc[i][j]);
    }
    __syncthreads();
  }

#pragma unroll
  for (int i = 0; i < 2; i++)
#pragma unroll
    for (int j = 0; j < 4; j++)
      wmma::store_matrix_sync(C + (size_t)(m0 + wm + i * 16) * N + n0 + wn + j * 16,
                              acc[i][j], N, wmma::mem_row_major);
}

// ---------------------------------------------------------------------------
// Candidate top-48 (coarse) -> SERIAL fp32 rescore (Eigen-order) ->
// top-16 with jax tie-break -> emulated softmax -> outputs.
// Selection rounds now use packed u64 warp-shuffle argmax (2 syncs/round),
// identical winner semantics: max value, tie -> lower index.
// ---------------------------------------------------------------------------
__device__ __forceinline__ unsigned long long pack_key(float v, int idx) {
  unsigned u = __float_as_uint(v);
  u = (u & 0x80000000u) ? ~u : (u | 0x80000000u);   // sortable ordering
  return ((unsigned long long)u << 14) | (unsigned)(16383 - idx);
}

__global__ __launch_bounds__(256) void refine_topk_kernel(
    const float* __restrict__ coarse, const float* __restrict__ x,
    const float* __restrict__ ctx, const float* __restrict__ neurons,
    const float* __restrict__ gate,
    float* __restrict__ out_y, float* __restrict__ out_idx,
    float* __restrict__ out_w, float* __restrict__ out_sel) {
  const int t = blockIdx.x;
  const int tid = threadIdx.x;
  const int lane = tid & 31;
  const int warp = tid >> 5;

  __shared__ float x_s[Dn];
  __shared__ float c_s[Dn];
  __shared__ float nbuf[8][Dn];     // 32KB: 8 staged neuron rows
  __shared__ unsigned long long wk[8];
  __shared__ int cand[NCAND];
  __shared__ float resc[NCAND];
  __shared__ float scratch[16];
  __shared__ int topi[TOPK];
  __shared__ float wts[TOPK];

  {
    const float* xr = x + (size_t)t * Dn;
    const float* cr = ctx + (size_t)t * Dn;
    for (int d = tid * 4; d < Dn; d += 256 * 4) {
      *(float4*)&x_s[d] = *(const float4*)(xr + d);
      *(float4*)&c_s[d] = *(const float4*)(cr + d);
    }
  }
  __syncthreads();

  // ---- Coarse top-NCAND candidate selection (warp-shuffle rounds) ----
  float sv[64];
  {
    const float* sr = coarse + (size_t)t * NNEUR;
#pragma unroll
    for (int j = 0; j < 64; j++) sv[j] = sr[j * 256 + tid];
  }
  float bv = -INFINITY;
  int bj = 0;
#pragma unroll
  for (int j = 0; j < 64; j++)      // strict > keeps lowest j on tie
    if (sv[j] > bv) { bv = sv[j]; bj = j; }

  for (int r = 0; r < NCAND; r++) {
    unsigned long long key = pack_key(bv, bj * 256 + tid);
#pragma unroll
    for (int off = 16; off; off >>= 1) {
      unsigned long long o = __shfl_xor_sync(0xffffffffu, key, off);
      if (o > key) key = o;
    }
    if (lane == 0) wk[warp] = key;
    __syncthreads();
    unsigned long long best = wk[0];
#pragma unroll
    for (int w = 1; w < 8; w++)
      if (wk[w] > best) best = wk[w];
    const int widx = 16383 - (int)(best & 0x3FFFull);
    if (tid == 0) cand[r] = widx;
    if ((widx & 255) == tid) {
      sv[widx >> 8] = -INFINITY;
      bv = -INFINITY; bj = 0;
#pragma unroll
      for (int j = 0; j < 64; j++)
        if (sv[j] > bv) { bv = sv[j]; bj = j; }
    }
    __syncthreads();
  }

  // ---- Serial rescore: waves of 8 candidates ----
  const float w0 = gate[2 * t], w1 = gate[2 * t + 1];
  for (int wave = 0; wave < NCAND / 8; wave++) {
    const int ci = wave * 8 + warp;
    const float* nr = neurons + (size_t)cand[ci] * Dn;
    for (int d = lane * 4; d < Dn; d += 32 * 4)
      *(float4*)&nbuf[warp][d] = *(const float4*)(nr + d);
    __syncthreads();
    if (tid < 16) {
      const int c = tid >> 1;
      const float* vrow = (tid & 1) ? c_s : x_s;
      float acc = 0.f;
      for (int d = 0; d < Dn; d++)                 // serial ascending FMA
        acc = __fmaf_rn(vrow[d], nbuf[c][d], acc);
      scratch[tid] = acc;
    }
    __syncthreads();
    if (tid < 8) {
      const float tsr = scratch[2 * tid];          // fp32 token score
      const float csr = scratch[2 * tid + 1];      // fp32 context score
      resc[wave * 8 + tid] = __fadd_rn(__fmul_rn(w0, tsr), __fmul_rn(w1, csr));
    }
    __syncthreads();
  }

  // ---- Top-16 among NCAND: value desc, tie -> lower index ----
  if (tid == 0) {
    float v[NCAND];
    int id[NCAND];
#pragma unroll
    for (int cc = 0; cc < NCAND; cc++) { v[cc] = resc[cc]; id[cc] = cand[cc]; }
    for (int a = 0; a < TOPK; a++) {
      int best = a;
      for (int b2 = a + 1; b2 < NCAND; b2++) {
        if (v[b2] > v[best] || (v[b2] == v[best] && id[b2] < id[best])) best = b2;
      }
      const float tv = v[a]; v[a] = v[best]; v[best] = tv;
      const int ti2 = id[a]; id[a] = id[best]; id[best] = ti2;
    }
    // Emulated softmax over top-16: serial ascending sum
    const float mx = v[0];
    float e[TOPK];
    float s = 0.f;
#pragma unroll
    for (int kk = 0; kk < TOPK; kk++) {
      e[kk] = exp_acc(__fsub_rn(v[kk], mx));
      s = __fadd_rn(s, e[kk]);
    }
#pragma unroll
    for (int kk = 0; kk < TOPK; kk++) {
      topi[kk] = id[kk];
      wts[kk] = __fdiv_rn(e[kk], s);
    }
  }
  __syncthreads();

  // ---- Outputs ----
  if (tid < TOPK) {
    out_idx[t * TOPK + tid] = (float)topi[tid];
    out_w[t * TOPK + tid] = wts[tid];
    out_sel[(size_t)t * NNEUR + topi[tid]] = wts[tid];
  }
  for (int d = tid; d < Dn; d += 256) {
    float a = 0.f;
#pragma unroll
    for (int kk = 0; kk < TOPK; kk++)   // serial ascending k (einsum order)
      a = __fmaf_rn(wts[kk], neurons[(size_t)topi[kk] * Dn + d], a);
    out_y[(size_t)t * Dn + d] = a;
  }
}

// ---------------------------------------------------------------------------
// Launch
// ---------------------------------------------------------------------------
extern "C" void kernel_launch(void* const* d_in, const int* in_sizes, int n_in,
                              void* d_out, int out_size) {
  (void)in_sizes; (void)n_in; (void)out_size;
  const float* x       = (const float*)d_in[0];
  const float* neurons = (const float*)d_in[1];
  const float* q_w     = (const float*)d_in[2];
  const float* q_b     = (const float*)d_in[3];
  const float* k_w     = (const float*)d_in[4];
  const float* k_b     = (const float*)d_in[5];
  const float* v_w     = (const float*)d_in[6];
  const float* v_b     = (const float*)d_in[7];
  const float* path_w  = (const float*)d_in[8];
  const float* path_b  = (const float*)d_in[9];
  float* out = (float*)d_out;

  float *gq, *gk, *gv, *gctx, *ggate, *gbig;
  __nv_bfloat16 *gyb, *gnb;
  cudaGetSymbolAddress((void**)&gq, g_q);
  cudaGetSymbolAddress((void**)&gk, g_k);
  cudaGetSymbolAddress((void**)&gv, g_v);
  cudaGetSymbolAddress((void**)&gctx, g_ctx);
  cudaGetSymbolAddress((void**)&ggate, g_gate);
  cudaGetSymbolAddress((void**)&gbig, g_big);
  cudaGetSymbolAddress((void**)&gyb, g_yb);
  cudaGetSymbolAddress((void**)&gnb, g_nb);

  // Opt-in to >48KB dynamic smem (idempotent; host-side, not captured)
  cudaFuncSetAttribute(attn_logits_v2,
                       cudaFuncAttributeMaxDynamicSharedMemorySize, LOG2_SMEM);
  cudaFuncSetAttribute(bf16_gemm_coarse,
                       cudaFuncAttributeMaxDynamicSharedMemorySize, COARSE_SMEM);

  // 0) bf16 neurons for the coarse tensor-core GEMM
  const int n4 = (NNEUR * Dn) / 4;
  convert_bf16_kernel<<<(n4 + 255) / 256, 256>>>(neurons, gnb, n4);

  // 1) QKV projections (serial-k fp32 SGEMM, reg-prefetch) — rank-critical
  dim3 qkv_grid(Dn / 128, MTOK / 128);  // (8, 32)
  sgemm128<false, true><<<qkv_grid, 256>>>(x, q_w, q_b, gq, MTOK, Dn, Dn);
  sgemm128<false, true><<<qkv_grid, 256>>>(x, k_w, k_b, gk, MTOK, Dn, Dn);
  sgemm128<false, true><<<qkv_grid, 256>>>(x, v_w, v_b, gv, MTOK, Dn, Dn);

  // 2) Attention: vectorized serial logits -> serial-sum softmax -> serial AV
  attn_logits_v2<<<dim3(8, 8, Bn * Hn), 256, LOG2_SMEM>>>(gq, gk, gbig);
  softmax_serial<<<(Bn * Hn * Sn) / 8, 256>>>(gbig);
  attn_av_kernel<<<dim3(Sn / 64, Bn * Hn), 128>>>(gbig, gv, gctx);

  // 3) Serial gate (stored) + bf16 y for the coarse GEMM
  gate_combine_serial<<<MTOK, 256>>>(x, gctx, path_w, path_b, gyb, ggate);

  // 4) Coarse scores on tensor cores (cp.async pipelined; nomination only)
  bf16_gemm_coarse<<<dim3(NNEUR / 128, MTOK / 128), 256, COARSE_SMEM>>>(
      gyb, gnb, gbig, MTOK, NNEUR, Dn);

  // 5) Candidates -> serial-emulated rescore -> top-16 -> outputs
  const size_t off_idx = (size_t)MTOK * Dn;
  const size_t off_w   = off_idx + (size_t)MTOK * TOPK;
  const size_t off_sel = off_w + (size_t)MTOK * TOPK;
  cudaMemsetAsync(out + off_sel, 0, (size_t)MTOK * NNEUR * sizeof(float));
  refine_topk_kernel<<<MTOK, 256>>>(gbig, x, gctx, neurons, ggate,
                                    out, out + off_idx, out + off_w,
                                    out + off_sel);
}